// round 11
// baseline (speedup 1.0000x reference)
#include <cuda_runtime.h>
#include <cuda_fp16.h>
#include <float.h>
#include <math.h>

// CapsuleConv2d: B=2, Cin=128, H=W=32, weight [O=16,L=16,M=16,3,3]
// 1 CTA per (b,h,w), 256 threads, 2 CTAs/SM (16 warps).
// Priors: split by rows — lower half threads do g=0..3, upper g=4..7;
//         each thread computes 2 columns (tid&127, +128) -> xs LDS amortized 2x.
//         fp32 f32x2 FMA, split chains; results stored fp16 to smem su[n][col].
// Routing: 1 column per thread (col = tid), R8-style direct half2 row reads,
//         v replicated in regs, per-iter cross-lane = 4 + 15 + 16 shfl.

__device__ float4 g_wT4[9 * 4 * 256];  // [(p*4+q)*256 + ol] = W[ol][4q..4q+3][p]

__global__ void wt_transpose(const float* __restrict__ w) {
    int idx = blockIdx.x * 256 + threadIdx.x;   // 9216 total
    int p  = idx >> 10;
    int q  = (idx >> 8) & 3;
    int ol = idx & 255;
    g_wT4[idx] = make_float4(w[(ol * 16 + 4 * q + 0) * 9 + p],
                             w[(ol * 16 + 4 * q + 1) * 9 + p],
                             w[(ol * 16 + 4 * q + 2) * 9 + p],
                             w[(ol * 16 + 4 * q + 3) * 9 + p]);
}

__device__ __forceinline__ unsigned long long fma2(unsigned long long a,
                                                   unsigned long long b,
                                                   unsigned long long c) {
    unsigned long long d;
    asm("fma.rn.f32x2 %0, %1, %2, %3;" : "=l"(d) : "l"(a), "l"(b), "l"(c));
    return d;
}
__device__ __forceinline__ unsigned long long add2(unsigned long long a,
                                                   unsigned long long b) {
    unsigned long long d;
    asm("add.rn.f32x2 %0, %1, %2;" : "=l"(d) : "l"(a), "l"(b));
    return d;
}

#define USTRIDE_H 264   // su row stride in halfs (528 B): conflict-free phases

__global__ __launch_bounds__(256, 2)
void capsule_kernel(const float* __restrict__ x, float* __restrict__ out) {
    extern __shared__ __align__(16) float smem[];
    float* xs = smem;                     // [1152] patch fp32
    float* pm = smem + 1152;              // [512] vmean partials: pm[half*256+col]
    __half* su = reinterpret_cast<__half*>(smem + 1152 + 512);  // 72*USTRIDE_H

    const unsigned FULL = 0xffffffffu;
    const int tid  = threadIdx.x;         // routing col
    const int half_id = tid >> 7;         // 0 lower (g 0..3), 1 upper (g 4..7)
    const int t    = tid & 127;           // priors column base
    const int lane = tid & 15;            // l
    const int bid = blockIdx.x;
    const int b = bid >> 10;
    const int h = (bid >> 5) & 31;
    const int w = bid & 31;

    // Stage 3x3 patch (zero-padded): 9 pixels x 128 channels
    for (int idx = tid; idx < 9 * 128; idx += 256) {
        int p = idx >> 7;
        int c = idx & 127;
        int hh = h + p / 3 - 1;
        int ww = w + p % 3 - 1;
        float v = 0.f;
        if ((unsigned)hh < 32u && (unsigned)ww < 32u)
            v = x[((b * 128 + c) * 32 + hh) * 32 + ww];
        xs[idx] = v;
    }
    __syncthreads();

    // ---- priors: this thread does 4 g's (its half) x 9 p's, 2 cols ----
    float vmA = 0.f, vmB = 0.f;
    const int goff = half_id * 4;
    const ulonglong2* xs2 = reinterpret_cast<const ulonglong2*>(xs);
    const ulonglong2* wp = reinterpret_cast<const ulonglong2*>(g_wT4);
#pragma unroll
    for (int p = 0; p < 9; p++) {
        ulonglong2 wa0 = wp[(p * 4 + 0) * 256 + t];
        ulonglong2 wa1 = wp[(p * 4 + 1) * 256 + t];
        ulonglong2 wa2 = wp[(p * 4 + 2) * 256 + t];
        ulonglong2 wa3 = wp[(p * 4 + 3) * 256 + t];
        ulonglong2 wb0 = wp[(p * 4 + 0) * 256 + t + 128];
        ulonglong2 wb1 = wp[(p * 4 + 1) * 256 + t + 128];
        ulonglong2 wb2 = wp[(p * 4 + 2) * 256 + t + 128];
        ulonglong2 wb3 = wp[(p * 4 + 3) * 256 + t + 128];
#pragma unroll
        for (int gg = 0; gg < 4; gg++) {
            int g = goff + gg;
            ulonglong2 A  = xs2[p * 32 + g * 4 + 0];
            ulonglong2 Bq = xs2[p * 32 + g * 4 + 1];
            ulonglong2 C  = xs2[p * 32 + g * 4 + 2];
            ulonglong2 D  = xs2[p * 32 + g * 4 + 3];
            unsigned long long a0 = fma2(A.x,  wa0.x, 0ull);
            unsigned long long a1 = fma2(A.y,  wa0.y, 0ull);
            unsigned long long b0 = fma2(A.x,  wb0.x, 0ull);
            unsigned long long b1 = fma2(A.y,  wb0.y, 0ull);
            a0 = fma2(Bq.x, wa1.x, a0);  a1 = fma2(Bq.y, wa1.y, a1);
            b0 = fma2(Bq.x, wb1.x, b0);  b1 = fma2(Bq.y, wb1.y, b1);
            a0 = fma2(C.x,  wa2.x, a0);  a1 = fma2(C.y,  wa2.y, a1);
            b0 = fma2(C.x,  wb2.x, b0);  b1 = fma2(C.y,  wb2.y, b1);
            a0 = fma2(D.x,  wa3.x, a0);  a1 = fma2(D.y,  wa3.y, a1);
            b0 = fma2(D.x,  wb3.x, b0);  b1 = fma2(D.y,  wb3.y, b1);
            unsigned long long sa = add2(a0, a1);
            unsigned long long sb = add2(b0, b1);
            float loA, hiA, loB, hiB;
            asm("mov.b64 {%0, %1}, %2;" : "=f"(loA), "=f"(hiA) : "l"(sa));
            asm("mov.b64 {%0, %1}, %2;" : "=f"(loB), "=f"(hiB) : "l"(sb));
            float sA = loA + hiA;
            float sB = loB + hiB;
            int n = g * 9 + p;
            su[n * USTRIDE_H + t]       = __float2half_rn(sA);
            su[n * USTRIDE_H + t + 128] = __float2half_rn(sB);
            vmA += sA;
            vmB += sB;
        }
    }
    pm[half_id * 256 + t]       = vmA;
    pm[half_id * 256 + t + 128] = vmB;
    __syncthreads();

    // ---- routing: col = tid ----
    const int colbase = tid & 0xF0;      // go*16
    const float vmean = pm[tid] + pm[256 + tid];

    // rows2[j*8+i] = half2(u[16j+lane][colbase+2i], u[..][colbase+2i+1])
    __half2 rows2[40];
#pragma unroll
    for (int j = 0; j < 5; j++) {
        int n = 16 * j + lane;
        if (n >= 72) n -= 72;            // wrap; masked later (e4=0)
        const uint4* rp = reinterpret_cast<const uint4*>(su + n * USTRIDE_H + colbase);
        uint4 q0 = rp[0];                // halfs 0..7
        uint4 q1 = rp[1];                // halfs 8..15
        rows2[j * 8 + 0] = *reinterpret_cast<__half2*>(&q0.x);
        rows2[j * 8 + 1] = *reinterpret_cast<__half2*>(&q0.y);
        rows2[j * 8 + 2] = *reinterpret_cast<__half2*>(&q0.z);
        rows2[j * 8 + 3] = *reinterpret_cast<__half2*>(&q0.w);
        rows2[j * 8 + 4] = *reinterpret_cast<__half2*>(&q1.x);
        rows2[j * 8 + 5] = *reinterpret_cast<__half2*>(&q1.y);
        rows2[j * 8 + 6] = *reinterpret_cast<__half2*>(&q1.z);
        rows2[j * 8 + 7] = *reinterpret_cast<__half2*>(&q1.w);
    }

    // initial v, replicated across the 16-lane group
    float v_own = vmean * (1.f / 72.f);
    float vv[16];
#pragma unroll
    for (int k = 0; k < 16; k++) vv[k] = __shfl_sync(FULL, v_own, k, 16);

    float ov = 0.f;
#pragma unroll
    for (int it = 0; it < 3; it++) {
        float sq = 0.f;
#pragma unroll
        for (int k = 0; k < 16; k++) sq = fmaf(vv[k], vv[k], sq);
        float rn = rsqrtf(fmaxf(sq, 1e-24f));

        float e[5];
#pragma unroll
        for (int j = 0; j < 5; j++) {
            float d = 0.f;
#pragma unroll
            for (int i = 0; i < 8; i++) {
                float2 f = __half22float2(rows2[j * 8 + i]);
                d = fmaf(f.x, vv[2 * i], d);
                d = fmaf(f.y, vv[2 * i + 1], d);
            }
            e[j] = __expf(d * rn);
        }
        if (lane >= 8) e[4] = 0.f;

        float ssum = ((e[0] + e[1]) + (e[2] + e[3])) + e[4];
        ssum += __shfl_xor_sync(FULL, ssum, 8);
        ssum += __shfl_xor_sync(FULL, ssum, 4);
        ssum += __shfl_xor_sync(FULL, ssum, 2);
        ssum += __shfl_xor_sync(FULL, ssum, 1);

        float a[16];
#pragma unroll
        for (int i = 0; i < 8; i++) {
            float ax = 0.f, ay = 0.f;
#pragma unroll
            for (int j = 0; j < 5; j++) {
                float2 f = __half22float2(rows2[j * 8 + i]);
                ax = fmaf(e[j], f.x, ax);
                ay = fmaf(e[j], f.y, ay);
            }
            a[2 * i] = ax;
            a[2 * i + 1] = ay;
        }

        // reduce-scatter: lane s ends with total a[s]
#pragma unroll
        for (int mm = 0; mm < 4; mm++) {
            const int m = 8 >> mm;
            bool up = (lane & m) != 0;
#pragma unroll
            for (int i = 0; i < 16; i++) {
                if (i >= m) continue;
                float send = up ? a[i] : a[i + m];
                float got = __shfl_xor_sync(FULL, send, m);
                a[i] = (up ? a[i + m] : a[i]) + got;
            }
        }
        float vfin = __fdividef(a[0], ssum);

        if (it < 2) {
#pragma unroll
            for (int k = 0; k < 16; k++) vv[k] = __shfl_sync(FULL, vfin, k, 16);
        } else {
            float s2 = vfin * vfin;
            s2 += __shfl_xor_sync(FULL, s2, 8);
            s2 += __shfl_xor_sync(FULL, s2, 4);
            s2 += __shfl_xor_sync(FULL, s2, 2);
            s2 += __shfl_xor_sync(FULL, s2, 1);
            float norm = sqrtf(s2);
            ov = vfin * __fdividef(norm, 1.f + s2);
        }
    }

    out[((b * 256 + tid) * 32 + h) * 32 + w] = ov;
}

extern "C" void kernel_launch(void* const* d_in, const int* in_sizes, int n_in,
                              void* d_out, int out_size) {
    const float* x = (const float*)d_in[0];    // [2,128,32,32]
    const float* w = (const float*)d_in[1];    // [16,16,16,3,3]
    float* out = (float*)d_out;                // [2,256,32,32]

    const int smem_bytes = (1152 + 512) * 4 + 72 * USTRIDE_H * 2;  // 6656+38016=44672
    cudaFuncSetAttribute(capsule_kernel,
                         cudaFuncAttributeMaxDynamicSharedMemorySize, smem_bytes);

    wt_transpose<<<36, 256>>>(w);
    capsule_kernel<<<2048, 256, smem_bytes>>>(x, out);
}

// round 12
// speedup vs baseline: 1.0851x; 1.0851x over previous
#include <cuda_runtime.h>
#include <cuda_fp16.h>
#include <float.h>
#include <math.h>

// CapsuleConv2d: B=2, Cin=128, H=W=32, weight [O=16,L=16,M=16,3,3]
// 1 CTA per (b,h,w), 128 threads, thread computes TWO columns: ol = tid, tid+128.
//  - priors (fp32 f32x2 FMA) streamed to smem u[n][ol] in fp16 (38KB -> 3 CTAs/SM)
//  - routing: rows read as half2 ONCE per pass, unpacked ONCE to fp32 rows[80];
//    all 3 iterations run fp32 FMA only (no per-use cvt tax)
//  - per-iter cross-lane: 4 + 15 + 16 shfl within 16-lane groups

__device__ float4 g_wT4[9 * 4 * 256];  // [(p*4+q)*256 + ol] = W[ol][4q..4q+3][p]

__global__ void wt_transpose(const float* __restrict__ w) {
    int idx = blockIdx.x * 256 + threadIdx.x;   // 9216 total
    int p  = idx >> 10;
    int q  = (idx >> 8) & 3;
    int ol = idx & 255;
    g_wT4[idx] = make_float4(w[(ol * 16 + 4 * q + 0) * 9 + p],
                             w[(ol * 16 + 4 * q + 1) * 9 + p],
                             w[(ol * 16 + 4 * q + 2) * 9 + p],
                             w[(ol * 16 + 4 * q + 3) * 9 + p]);
}

__device__ __forceinline__ unsigned long long fma2(unsigned long long a,
                                                   unsigned long long b,
                                                   unsigned long long c) {
    unsigned long long d;
    asm("fma.rn.f32x2 %0, %1, %2, %3;" : "=l"(d) : "l"(a), "l"(b), "l"(c));
    return d;
}
__device__ __forceinline__ unsigned long long add2(unsigned long long a,
                                                   unsigned long long b) {
    unsigned long long d;
    asm("add.rn.f32x2 %0, %1, %2;" : "=l"(d) : "l"(a), "l"(b));
    return d;
}

#define USTRIDE_H 264   // row stride in halfs (528 B): conflict-free phase pattern

__global__ __launch_bounds__(128, 3)
void capsule_kernel(const float* __restrict__ x, float* __restrict__ out) {
    extern __shared__ __align__(16) float smem[];
    float* xs = smem;                                   // 9*128 patch (fp32)
    __half* su = reinterpret_cast<__half*>(smem + 1152); // 72 * USTRIDE_H halfs

    const unsigned FULL = 0xffffffffu;
    const int tid = threadIdx.x;     // colA = tid, colB = tid + 128
    const int lane = tid & 15;       // l
    const int grp = tid >> 4;        // o for colA (0..7); colB is grp+8
    const int bid = blockIdx.x;
    const int b = bid >> 10;
    const int h = (bid >> 5) & 31;
    const int w = bid & 31;

    // Stage 3x3 patch (zero-padded): 9 pixels x 128 channels
    for (int idx = tid; idx < 9 * 128; idx += 128) {
        int p = idx >> 7;
        int c = idx & 127;
        int hh = h + p / 3 - 1;
        int ww = w + p % 3 - 1;
        float v = 0.f;
        if ((unsigned)hh < 32u && (unsigned)ww < 32u)
            v = x[((b * 128 + c) * 32 + hh) * 32 + ww];
        xs[idx] = v;
    }
    __syncthreads();

    // ---- priors for BOTH columns; split FMA chains; each xs load feeds 2 cols ----
    float vmeanA = 0.f, vmeanB = 0.f;
    const ulonglong2* xs2 = reinterpret_cast<const ulonglong2*>(xs);
    const ulonglong2* wp = reinterpret_cast<const ulonglong2*>(g_wT4);
#pragma unroll
    for (int p = 0; p < 9; p++) {
        ulonglong2 wa0 = wp[(p * 4 + 0) * 256 + tid];
        ulonglong2 wa1 = wp[(p * 4 + 1) * 256 + tid];
        ulonglong2 wa2 = wp[(p * 4 + 2) * 256 + tid];
        ulonglong2 wa3 = wp[(p * 4 + 3) * 256 + tid];
        ulonglong2 wb0 = wp[(p * 4 + 0) * 256 + tid + 128];
        ulonglong2 wb1 = wp[(p * 4 + 1) * 256 + tid + 128];
        ulonglong2 wb2 = wp[(p * 4 + 2) * 256 + tid + 128];
        ulonglong2 wb3 = wp[(p * 4 + 3) * 256 + tid + 128];
#pragma unroll
        for (int g = 0; g < 8; g++) {
            ulonglong2 A  = xs2[p * 32 + g * 4 + 0];
            ulonglong2 Bq = xs2[p * 32 + g * 4 + 1];
            ulonglong2 C  = xs2[p * 32 + g * 4 + 2];
            ulonglong2 D  = xs2[p * 32 + g * 4 + 3];
            unsigned long long a0 = fma2(A.x,  wa0.x, 0ull);
            unsigned long long a1 = fma2(A.y,  wa0.y, 0ull);
            unsigned long long b0 = fma2(A.x,  wb0.x, 0ull);
            unsigned long long b1 = fma2(A.y,  wb0.y, 0ull);
            a0 = fma2(Bq.x, wa1.x, a0);  a1 = fma2(Bq.y, wa1.y, a1);
            b0 = fma2(Bq.x, wb1.x, b0);  b1 = fma2(Bq.y, wb1.y, b1);
            a0 = fma2(C.x,  wa2.x, a0);  a1 = fma2(C.y,  wa2.y, a1);
            b0 = fma2(C.x,  wb2.x, b0);  b1 = fma2(C.y,  wb2.y, b1);
            a0 = fma2(D.x,  wa3.x, a0);  a1 = fma2(D.y,  wa3.y, a1);
            b0 = fma2(D.x,  wb3.x, b0);  b1 = fma2(D.y,  wb3.y, b1);
            unsigned long long sa = add2(a0, a1);
            unsigned long long sb = add2(b0, b1);
            float loA, hiA, loB, hiB;
            asm("mov.b64 {%0, %1}, %2;" : "=f"(loA), "=f"(hiA) : "l"(sa));
            asm("mov.b64 {%0, %1}, %2;" : "=f"(loB), "=f"(hiB) : "l"(sb));
            float sA = loA + hiA;
            float sB = loB + hiB;
            int n = g * 9 + p;
            su[n * USTRIDE_H + tid]       = __float2half_rn(sA);
            su[n * USTRIDE_H + tid + 128] = __float2half_rn(sB);
            vmeanA += sA;
            vmeanB += sB;
        }
    }
    __syncthreads();

    // ---- routing: two sequential passes (colA = grp, colB = grp+8) ----
#pragma unroll 1
    for (int pass = 0; pass < 2; pass++) {
        const int col = tid + pass * 128;
        const int go = grp + pass * 8;
        const float vmean = pass ? vmeanB : vmeanA;

        // read rows ONCE, unpack ONCE to fp32: rows[j*16+k] = u[16j+lane][go*16+k]
        float rows[80];
#pragma unroll
        for (int j = 0; j < 5; j++) {
            int n = 16 * j + lane;
            if (n >= 72) n -= 72;            // wrap; masked later (e4=0)
            const uint4* rp = reinterpret_cast<const uint4*>(su + n * USTRIDE_H + go * 16);
            uint4 q0 = rp[0];                // halfs 0..7
            uint4 q1 = rp[1];                // halfs 8..15
            float2 f;
            f = __half22float2(*reinterpret_cast<__half2*>(&q0.x));
            rows[j * 16 + 0] = f.x;  rows[j * 16 + 1] = f.y;
            f = __half22float2(*reinterpret_cast<__half2*>(&q0.y));
            rows[j * 16 + 2] = f.x;  rows[j * 16 + 3] = f.y;
            f = __half22float2(*reinterpret_cast<__half2*>(&q0.z));
            rows[j * 16 + 4] = f.x;  rows[j * 16 + 5] = f.y;
            f = __half22float2(*reinterpret_cast<__half2*>(&q0.w));
            rows[j * 16 + 6] = f.x;  rows[j * 16 + 7] = f.y;
            f = __half22float2(*reinterpret_cast<__half2*>(&q1.x));
            rows[j * 16 + 8] = f.x;  rows[j * 16 + 9] = f.y;
            f = __half22float2(*reinterpret_cast<__half2*>(&q1.y));
            rows[j * 16 + 10] = f.x; rows[j * 16 + 11] = f.y;
            f = __half22float2(*reinterpret_cast<__half2*>(&q1.z));
            rows[j * 16 + 12] = f.x; rows[j * 16 + 13] = f.y;
            f = __half22float2(*reinterpret_cast<__half2*>(&q1.w));
            rows[j * 16 + 14] = f.x; rows[j * 16 + 15] = f.y;
        }

        // initial v, replicated across the 16-lane group
        float v_own = vmean * (1.f / 72.f);
        float vv[16];
#pragma unroll
        for (int k = 0; k < 16; k++) vv[k] = __shfl_sync(FULL, v_own, k, 16);

        float ov = 0.f;
#pragma unroll
        for (int it = 0; it < 3; it++) {
            float sq = 0.f;
#pragma unroll
            for (int k = 0; k < 16; k++) sq = fmaf(vv[k], vv[k], sq);
            float rn = rsqrtf(fmaxf(sq, 1e-24f));

            float e[5];
#pragma unroll
            for (int j = 0; j < 5; j++) {
                float d = 0.f;
#pragma unroll
                for (int k = 0; k < 16; k++) d = fmaf(rows[j * 16 + k], vv[k], d);
                e[j] = __expf(d * rn);
            }
            if (lane >= 8) e[4] = 0.f;

            float ssum = ((e[0] + e[1]) + (e[2] + e[3])) + e[4];
            ssum += __shfl_xor_sync(FULL, ssum, 8);
            ssum += __shfl_xor_sync(FULL, ssum, 4);
            ssum += __shfl_xor_sync(FULL, ssum, 2);
            ssum += __shfl_xor_sync(FULL, ssum, 1);

            float a[16];
#pragma unroll
            for (int k = 0; k < 16; k++) {
                float acc = e[0] * rows[k];
                acc = fmaf(e[1], rows[16 + k], acc);
                acc = fmaf(e[2], rows[32 + k], acc);
                acc = fmaf(e[3], rows[48 + k], acc);
                acc = fmaf(e[4], rows[64 + k], acc);
                a[k] = acc;
            }

            // reduce-scatter: lane s ends with total a[s]
#pragma unroll
            for (int mm = 0; mm < 4; mm++) {
                const int m = 8 >> mm;
                bool up = (lane & m) != 0;
#pragma unroll
                for (int i = 0; i < 16; i++) {
                    if (i >= m) continue;
                    float send = up ? a[i] : a[i + m];
                    float got = __shfl_xor_sync(FULL, send, m);
                    a[i] = (up ? a[i + m] : a[i]) + got;
                }
            }
            float vfin = __fdividef(a[0], ssum);

            if (it < 2) {
#pragma unroll
                for (int k = 0; k < 16; k++) vv[k] = __shfl_sync(FULL, vfin, k, 16);
            } else {
                float s2 = vfin * vfin;
                s2 += __shfl_xor_sync(FULL, s2, 8);
                s2 += __shfl_xor_sync(FULL, s2, 4);
                s2 += __shfl_xor_sync(FULL, s2, 2);
                s2 += __shfl_xor_sync(FULL, s2, 1);
                float norm = sqrtf(s2);
                ov = vfin * __fdividef(norm, 1.f + s2);
            }
        }

        out[((b * 256 + col) * 32 + h) * 32 + w] = ov;
    }
}

extern "C" void kernel_launch(void* const* d_in, const int* in_sizes, int n_in,
                              void* d_out, int out_size) {
    const float* x = (const float*)d_in[0];    // [2,128,32,32]
    const float* w = (const float*)d_in[1];    // [16,16,16,3,3]
    float* out = (float*)d_out;                // [2,256,32,32]

    const int smem_bytes = 1152 * 4 + 72 * USTRIDE_H * 2;   // 4608 + 38016 = 42624 B
    cudaFuncSetAttribute(capsule_kernel,
                         cudaFuncAttributeMaxDynamicSharedMemorySize, smem_bytes);

    wt_transpose<<<36, 256>>>(w);
    capsule_kernel<<<2048, 128, smem_bytes>>>(x, out);
}

// round 13
// speedup vs baseline: 1.6368x; 1.5084x over previous
#include <cuda_runtime.h>
#include <cuda_fp16.h>
#include <float.h>
#include <math.h>

// CapsuleConv2d: B=2, Cin=128, H=W=32, weight [O=16,L=16,M=16,3,3]
// 1 CTA per (b,h,w), 128 threads (4 warps).
// PRIORS ON TENSOR CORES: per p, C_p[256(ol) x 8(g)] = W_p[256x16] * XS_p[16x8]
//   as mma.sync.m16n8k16.row.col.f32.f16.f16.f32; warp w owns ol-tiles 4w..4w+3.
//   A-fragments precomputed in-register-layout in global (g_wfrag), B-fragments
//   read directly from the fp16 patch in smem. C scattered to su[n][ol] fp16.
// ROUTING (unchanged R12): per-thread fp32 rows, v replicated, 2 passes,
//   per-iter cross-lane = 4 + 15 + 16 shfl; v0 = row-sums + reduce-scatter.

__device__ uint4 g_wfrag[9 * 16 * 32];  // [(p*16+tile)*32 + lane] = {a0,a1,a2,a3}

__global__ void wt_frag(const float* __restrict__ w) {
    int idx = blockIdx.x * 256 + threadIdx.x;   // 4608 total
    if (idx >= 4608) return;
    int p    = idx >> 9;          // 0..8
    int tile = (idx >> 5) & 15;   // ol tile
    int lane = idx & 31;
    int gid  = lane >> 2;         // row group
    int kb   = (lane & 3) * 2;    // col base (k)
    // A[r][k] = W[ol=tile*16+r][m=k][p] = w[((tile*16+r)*16 + k)*9 + p]
    const int base = tile * 16;
    auto W = [&](int r, int k) { return w[((base + r) * 16 + k) * 9 + p]; };
    __half2 a0 = __floats2half2_rn(W(gid,     kb),     W(gid,     kb + 1));
    __half2 a1 = __floats2half2_rn(W(gid + 8, kb),     W(gid + 8, kb + 1));
    __half2 a2 = __floats2half2_rn(W(gid,     kb + 8), W(gid,     kb + 9));
    __half2 a3 = __floats2half2_rn(W(gid + 8, kb + 8), W(gid + 8, kb + 9));
    uint4 o;
    o.x = *reinterpret_cast<unsigned*>(&a0);
    o.y = *reinterpret_cast<unsigned*>(&a1);
    o.z = *reinterpret_cast<unsigned*>(&a2);
    o.w = *reinterpret_cast<unsigned*>(&a3);
    g_wfrag[idx] = o;
}

#define USTRIDE_H 264   // su row stride in halfs (528 B)

__global__ __launch_bounds__(128, 3)
void capsule_kernel(const float* __restrict__ x, float* __restrict__ out) {
    extern __shared__ __align__(16) __half smemh[];
    __half* xsh = smemh;            // [9*128] patch fp16
    __half* su  = smemh + 1152;     // [72 * USTRIDE_H] priors fp16

    const unsigned FULL = 0xffffffffu;
    const int tid = threadIdx.x;
    const int lane = tid & 15;       // l (16-group lane)
    const int grp = tid >> 4;        // o for pass A
    const int wid = tid >> 5;        // warp id
    const int l32 = tid & 31;
    const int gid = l32 >> 2;        // mma row group
    const int kb  = (l32 & 3) * 2;   // mma k/g base
    const int bid = blockIdx.x;
    const int b = bid >> 10;
    const int h = (bid >> 5) & 31;
    const int w = bid & 31;

    // Stage 3x3 patch (zero-padded) as fp16: 9 pixels x 128 channels
    for (int idx = tid; idx < 9 * 128; idx += 128) {
        int p = idx >> 7;
        int c = idx & 127;
        int hh = h + p / 3 - 1;
        int ww = w + p % 3 - 1;
        float v = 0.f;
        if ((unsigned)hh < 32u && (unsigned)ww < 32u)
            v = x[((b * 128 + c) * 32 + hh) * 32 + ww];
        xsh[idx] = __float2half_rn(v);
    }
    __syncthreads();

    // ---- priors via tensor cores ----
#pragma unroll
    for (int p = 0; p < 9; p++) {
        // B fragment (16x8 col-major): b0={B[kb][gid],B[kb+1][gid]}, b1 = k+8
        unsigned b0 = *reinterpret_cast<const unsigned*>(&xsh[p * 128 + gid * 16 + kb]);
        unsigned b1 = *reinterpret_cast<const unsigned*>(&xsh[p * 128 + gid * 16 + kb + 8]);
#pragma unroll
        for (int tt = 0; tt < 4; tt++) {
            int tile = wid * 4 + tt;
            uint4 af = g_wfrag[(p * 16 + tile) * 32 + l32];
            float d0, d1, d2, d3;
            asm volatile(
                "mma.sync.aligned.m16n8k16.row.col.f32.f16.f16.f32 "
                "{%0,%1,%2,%3}, {%4,%5,%6,%7}, {%8,%9}, {%10,%11,%12,%13};"
                : "=f"(d0), "=f"(d1), "=f"(d2), "=f"(d3)
                : "r"(af.x), "r"(af.y), "r"(af.z), "r"(af.w),
                  "r"(b0), "r"(b1),
                  "f"(0.f), "f"(0.f), "f"(0.f), "f"(0.f));
            // C: d0=(r=gid, g=kb) d1=(gid, kb+1) d2=(gid+8, kb) d3=(gid+8, kb+1)
            int ol0 = tile * 16 + gid;
            int n0  = kb * 9 + p;                 // g=kb
            su[n0 * USTRIDE_H + ol0]             = __float2half_rn(d0);
            su[(n0 + 9) * USTRIDE_H + ol0]       = __float2half_rn(d1);
            su[n0 * USTRIDE_H + ol0 + 8]         = __float2half_rn(d2);
            su[(n0 + 9) * USTRIDE_H + ol0 + 8]   = __float2half_rn(d3);
        }
    }
    __syncthreads();

    // ---- routing: two sequential passes (colA = grp, colB = grp+8) ----
#pragma unroll 1
    for (int pass = 0; pass < 2; pass++) {
        const int col = tid + pass * 128;
        const int go = grp + pass * 8;

        // read rows ONCE, unpack ONCE: rows[j*16+k] = u[16j+lane][go*16+k]
        float rows[80];
#pragma unroll
        for (int j = 0; j < 5; j++) {
            int n = 16 * j + lane;
            if (n >= 72) n -= 72;            // wrap; excluded from sums, e4=0
            const uint4* rp = reinterpret_cast<const uint4*>(su + n * USTRIDE_H + go * 16);
            uint4 q0 = rp[0];
            uint4 q1 = rp[1];
            float2 f;
            f = __half22float2(*reinterpret_cast<__half2*>(&q0.x));
            rows[j * 16 + 0] = f.x;  rows[j * 16 + 1] = f.y;
            f = __half22float2(*reinterpret_cast<__half2*>(&q0.y));
            rows[j * 16 + 2] = f.x;  rows[j * 16 + 3] = f.y;
            f = __half22float2(*reinterpret_cast<__half2*>(&q0.z));
            rows[j * 16 + 4] = f.x;  rows[j * 16 + 5] = f.y;
            f = __half22float2(*reinterpret_cast<__half2*>(&q0.w));
            rows[j * 16 + 6] = f.x;  rows[j * 16 + 7] = f.y;
            f = __half22float2(*reinterpret_cast<__half2*>(&q1.x));
            rows[j * 16 + 8] = f.x;  rows[j * 16 + 9] = f.y;
            f = __half22float2(*reinterpret_cast<__half2*>(&q1.y));
            rows[j * 16 + 10] = f.x; rows[j * 16 + 11] = f.y;
            f = __half22float2(*reinterpret_cast<__half2*>(&q1.z));
            rows[j * 16 + 12] = f.x; rows[j * 16 + 13] = f.y;
            f = __half22float2(*reinterpret_cast<__half2*>(&q1.w));
            rows[j * 16 + 14] = f.x; rows[j * 16 + 15] = f.y;
        }

        // v0 = mean over n: local row sums (exclude wrapped row), reduce-scatter
        float a[16];
#pragma unroll
        for (int k = 0; k < 16; k++) {
            float s = ((rows[k] + rows[16 + k]) + (rows[32 + k] + rows[48 + k]));
            if (lane < 8) s += rows[64 + k];
            a[k] = s;
        }
#pragma unroll
        for (int mm = 0; mm < 4; mm++) {
            const int m = 8 >> mm;
            bool up = (lane & m) != 0;
#pragma unroll
            for (int i = 0; i < 16; i++) {
                if (i >= m) continue;
                float send = up ? a[i] : a[i + m];
                float got = __shfl_xor_sync(FULL, send, m);
                a[i] = (up ? a[i + m] : a[i]) + got;
            }
        }
        float v_own = a[0] * (1.f / 72.f);

        float vv[16];
#pragma unroll
        for (int k = 0; k < 16; k++) vv[k] = __shfl_sync(FULL, v_own, k, 16);

        float ov = 0.f;
#pragma unroll
        for (int it = 0; it < 3; it++) {
            float sq = 0.f;
#pragma unroll
            for (int k = 0; k < 16; k++) sq = fmaf(vv[k], vv[k], sq);
            float rn = rsqrtf(fmaxf(sq, 1e-24f));

            float e[5];
#pragma unroll
            for (int j = 0; j < 5; j++) {
                float d = 0.f;
#pragma unroll
                for (int k = 0; k < 16; k++) d = fmaf(rows[j * 16 + k], vv[k], d);
                e[j] = __expf(d * rn);
            }
            if (lane >= 8) e[4] = 0.f;

            float ssum = ((e[0] + e[1]) + (e[2] + e[3])) + e[4];
            ssum += __shfl_xor_sync(FULL, ssum, 8);
            ssum += __shfl_xor_sync(FULL, ssum, 4);
            ssum += __shfl_xor_sync(FULL, ssum, 2);
            ssum += __shfl_xor_sync(FULL, ssum, 1);

#pragma unroll
            for (int k = 0; k < 16; k++) {
                float acc = e[0] * rows[k];
                acc = fmaf(e[1], rows[16 + k], acc);
                acc = fmaf(e[2], rows[32 + k], acc);
                acc = fmaf(e[3], rows[48 + k], acc);
                acc = fmaf(e[4], rows[64 + k], acc);
                a[k] = acc;
            }

            // reduce-scatter: lane s ends with total a[s]
#pragma unroll
            for (int mm = 0; mm < 4; mm++) {
                const int m = 8 >> mm;
                bool up = (lane & m) != 0;
#pragma unroll
                for (int i = 0; i < 16; i++) {
                    if (i >= m) continue;
                    float send = up ? a[i] : a[i + m];
                    float got = __shfl_xor_sync(FULL, send, m);
                    a[i] = (up ? a[i + m] : a[i]) + got;
                }
            }
            float vfin = __fdividef(a[0], ssum);

            if (it < 2) {
#pragma unroll
                for (int k = 0; k < 16; k++) vv[k] = __shfl_sync(FULL, vfin, k, 16);
            } else {
                float s2 = vfin * vfin;
                s2 += __shfl_xor_sync(FULL, s2, 8);
                s2 += __shfl_xor_sync(FULL, s2, 4);
                s2 += __shfl_xor_sync(FULL, s2, 2);
                s2 += __shfl_xor_sync(FULL, s2, 1);
                float norm = sqrtf(s2);
                ov = vfin * __fdividef(norm, 1.f + s2);
            }
        }

        out[((b * 256 + col) * 32 + h) * 32 + w] = ov;
    }
}

extern "C" void kernel_launch(void* const* d_in, const int* in_sizes, int n_in,
                              void* d_out, int out_size) {
    const float* x = (const float*)d_in[0];    // [2,128,32,32]
    const float* w = (const float*)d_in[1];    // [16,16,16,3,3]
    float* out = (float*)d_out;                // [2,256,32,32]

    const int smem_bytes = (1152 + 72 * USTRIDE_H) * 2;   // 2304 + 38016 = 40320 B
    cudaFuncSetAttribute(capsule_kernel,
                         cudaFuncAttributeMaxDynamicSharedMemorySize, smem_bytes);

    wt_frag<<<18, 256>>>(w);
    capsule_kernel<<<2048, 128, smem_bytes>>>(x, out);
}